// round 15
// baseline (speedup 1.0000x reference)
#include <cuda_runtime.h>

#define RR 1040      // B*S segment rows
#define SS 65        // segments per batch
#define BB 16        // batch
#define DD 128       // feature dim
#define WW 256       // candidate positions per segment
#define TT 2176      // MAX_LEN_PAD (x time dim)
#define OUT_T 2048   // MAX_LEN_SEQ
#define NMAIN 888    // gather blocks (8 warps x 4 slots = 28416 slots/sweep)
#define NEMIT 130    // emit blocks (8 warps each = RR rows)
#define ZBLK 512     // zero-fill blocks appended to the EMIT grid

// Scratch (allocation-free requirement -> __device__ globals)
__device__ int  g_meta[2];             // [0]=total, [1]=L
__device__ int4 g_info[RR];            // {sc bits, ibase (=b*TT+soff), rowstart, count}
__device__ int4 g_rec[RR * WW];        // per-slot {gather base, lam bits, out base|-1, pad}

// ---------------------------------------------------------------------------
// k_prep: ONE block, 1024 threads. Metadata only (binary-search count —
// the proven-correct, proven-fast variant; prep arithmetic is NOT the
// bottleneck, per R10/R12/R14 invariance).
// Mask predicate is a prefix in w:  __fdiv_rn(w,sc) < lim  (IEEE division
// monotone in numerator; lim is an integer-valued float).
// ---------------------------------------------------------------------------
__global__ void __launch_bounds__(1024) k_prep(const float* __restrict__ scales,
                                               const int*   __restrict__ len_seq,
                                               const int*   __restrict__ len_seg_raw) {
    __shared__ int sseg[RR];
    __shared__ int soff[RR];
    __shared__ int s_wsum[32];
    __shared__ int s_wbase[32];
    const int tid  = threadIdx.x;
    const int lane = tid & 31;
    const int wid  = tid >> 5;

    for (int i = tid; i < RR; i += 1024) sseg[i] = len_seg_raw[i] + 32; // +MIN_LEN_SEG
    __syncthreads();

    if (wid < BB) {                      // warp-per-batch exclusive scan of 65 seg lens
        const int base = wid * SS;
        int carry = 0;
        #pragma unroll
        for (int c = 0; c < 3; c++) {
            const int s = c * 32 + lane;
            int v = (s < SS) ? sseg[base + s] : 0;
            int inc = v;
            #pragma unroll
            for (int d = 1; d < 32; d <<= 1) {
                const int n = __shfl_up_sync(0xffffffffu, inc, d);
                if (lane >= d) inc += n;
            }
            if (s < SS) soff[base + s] = carry + inc - v;
            carry += __shfl_sync(0xffffffffu, inc, 31);
        }
    }
    __syncthreads();

    // Two ordered rows per thread -> counts via 8-step binary search, local scan.
    int cnt[2], loc[2];
    int run = 0;
    #pragma unroll
    for (int j = 0; j < 2; j++) {
        const int r = tid * 2 + j;
        int c = 0;
        if (r < RR) {
            const float sc  = scales[r] + 0.5f;
            const int   off = soff[r];
            const int   ls  = len_seq[r / SS];
            const float lim = fminf((float)(sseg[r] - 1),
                                    (float)(ls - 1) - (float)off);
            int lo = 0, hi = WW;         // pred(w) = __fdiv_rn(w,sc) < lim, prefix-true
            #pragma unroll
            for (int it = 0; it < 8; it++) {
                const int mid = (lo + hi) >> 1;
                if (__fdiv_rn((float)mid, sc) < lim) lo = mid + 1; else hi = mid;
            }
            c = lo;
        }
        loc[j] = run; run += c; cnt[j] = c;
    }
    int inc = run;
    #pragma unroll
    for (int d = 1; d < 32; d <<= 1) {
        const int n = __shfl_up_sync(0xffffffffu, inc, d);
        if (lane >= d) inc += n;
    }
    const int texcl = inc - run;
    if (lane == 31) s_wsum[wid] = inc;
    __syncthreads();
    if (tid == 0) {
        int acc = 0;
        #pragma unroll
        for (int i = 0; i < 32; i++) { s_wbase[i] = acc; acc += s_wsum[i]; }
        g_meta[0] = acc;
        g_meta[1] = acc / BB;            // L = total // B
    }
    __syncthreads();
    const int base = s_wbase[wid] + texcl;
    #pragma unroll
    for (int j = 0; j < 2; j++) {
        const int r = tid * 2 + j;
        if (r < RR) {
            g_info[r] = make_int4(__float_as_int(scales[r] + 0.5f),
                                  (r / SS) * TT + soff[r],
                                  base + loc[j],
                                  cnt[j]);
        }
    }
}

// ---------------------------------------------------------------------------
// k_emit: blocks [0, NEMIT) = warp-per-row; lanes sweep w in [0, count):
//   rec = { g   = (ibase + floor(w/sc)) * 32,
//           lam = w/sc - floor(w/sc),
//           ob  = out float4-base for slot p = rs + w, or -1 if dropped }
// All divisions (fp32 lam + int p/L) live HERE, spread across 130 SMs, so
// k_main carries no division and no L dependence.
// Blocks [NEMIT, NEMIT+ZBLK) zero-fill the t >= L tail (out is poisoned).
// ---------------------------------------------------------------------------
__global__ void __launch_bounds__(256) k_emit(float* __restrict__ out) {
    const int bx = blockIdx.x;
    const int L  = g_meta[1];

    if (bx >= NEMIT) {                   // ---- zero-fill tail ----
        if (L >= OUT_T || L <= 0) return;
        const unsigned base = (unsigned)(bx - NEMIT) * 256u + threadIdx.x;
        const float4 z = make_float4(0.f, 0.f, 0.f, 0.f);
        #pragma unroll
        for (int j = 0; j < 8; j++) {
            const unsigned i = base + (unsigned)j * (ZBLK * 256u); // 1,048,576 float4
            const int t = (int)((i >> 5) & (OUT_T - 1));           // 32 float4 per row
            if (t >= L) ((float4*)out)[i] = z;
        }
        return;
    }
    if (L <= 0) return;

    const int r    = bx * 8 + (threadIdx.x >> 5);   // NEMIT*8 = RR exactly
    const int lane = threadIdx.x & 31;

    const int4  info  = g_info[r];
    const float sc    = __int_as_float(info.x);
    const int   ibase = info.y;
    const int   rs    = info.z;
    const int   cn    = info.w;

    for (int w = lane; w < cn; w += 32) {
        const float ws  = __fdiv_rn((float)w, sc);
        const float ifl = floorf(ws);
        const int   p   = rs + w;
        const int   bo  = p / L;
        const int   t   = p - bo * L;
        const int   ob  = (bo < BB && t < OUT_T) ? (bo * OUT_T + t) * (DD / 4) : -1;
        g_rec[p] = make_int4((ibase + (int)ifl) * (DD / 4),
                             __float_as_int(ws - ifl), ob, 0);
    }
}

// ---------------------------------------------------------------------------
// k_main: pure streaming gather. One warp = 4 consecutive slots:
// 4 uniform 16B record loads, 8 gather LDG.128, 4 predicated STG.128 (.cs).
// No smem, no search, no division, no L. Records past `total` are never
// dereferenced (predicated by p0+k < total).
// ---------------------------------------------------------------------------
__global__ void __launch_bounds__(256, 5)
k_main(const float* __restrict__ x,
       float* __restrict__ out) {
    const int total = g_meta[0];
    const int lane  = threadIdx.x & 31;
    const int gw    = blockIdx.x * 8 + (threadIdx.x >> 5);   // global warp id
    const float4* __restrict__ x4 = (const float4*)x;

    for (int p0 = gw * 4; p0 < total; p0 += NMAIN * 8 * 4) {
        const int4 r0 = g_rec[p0];
        const int4 r1 = g_rec[p0 + 1];
        const int4 r2 = g_rec[p0 + 2];
        const int4 r3 = g_rec[p0 + 3];
        const int   gx[4] = { r0.x, r1.x, r2.x, r3.x };
        const float lm[4] = { __int_as_float(r0.y), __int_as_float(r1.y),
                              __int_as_float(r2.y), __int_as_float(r3.y) };
        const int   ob[4] = { r0.z, r1.z, r2.z, r3.z };

        float4 a[4], c[4];
        int    vv[4];
        #pragma unroll
        for (int k = 0; k < 4; k++) {
            vv[k] = (p0 + k < total) && (ob[k] >= 0);
            if (vv[k]) {
                const int g = gx[k] + lane;
                a[k] = x4[g];
                c[k] = x4[g + (DD / 4)];
            }
        }
        #pragma unroll
        for (int k = 0; k < 4; k++) {
            if (vv[k]) {
                const float l = lm[k], m = 1.0f - l;
                float4 y;
                y.x = m * a[k].x + l * c[k].x;
                y.y = m * a[k].y + l * c[k].y;
                y.z = m * a[k].z + l * c[k].z;
                y.w = m * a[k].w + l * c[k].w;
                __stcs(((float4*)out) + ob[k] + lane, y);  // stream: keep x in L2
            }
        }
    }
}

// ---------------------------------------------------------------------------
extern "C" void kernel_launch(void* const* d_in, const int* in_sizes, int n_in,
                              void* d_out, int out_size) {
    const float* x           = (const float*)d_in[0];
    const float* scales      = (const float*)d_in[1];
    const int*   len_seq     = (const int*)d_in[2];
    const int*   len_seg_raw = (const int*)d_in[3];
    float*       out         = (float*)d_out;

    k_prep<<<1, 1024>>>(scales, len_seq, len_seg_raw);
    k_emit<<<NEMIT + ZBLK, 256>>>(out);
    k_main<<<NMAIN, 256>>>(x, out);
}

// round 16
// speedup vs baseline: 1.1580x; 1.1580x over previous
#include <cuda_runtime.h>

#define RR 1040      // B*S segment rows
#define SS 65        // segments per batch
#define BB 16        // batch
#define DD 128       // feature dim
#define WW 256       // candidate positions per segment
#define TT 2176      // MAX_LEN_PAD (x time dim)
#define OUT_T 2048   // MAX_LEN_SEQ
#define NMAIN 592    // 148 SMs x 4 resident blocks = exactly ONE wave
#define NF4   (BB * OUT_T * (DD / 4))   // 1,048,576 output float4s

// Scratch (allocation-free requirement -> __device__ globals)
__device__ int  g_meta[2];             // [0]=total, [1]=L
__device__ int4 g_info[RR];            // {sc bits, ibase (=b*TT+soff), rowstart, count}
__device__ int2 g_rec[RR * WW];        // per-slot {gather base g = ix*32, lam bits}

// ---------------------------------------------------------------------------
// k_prep: ONE block, 1024 threads. Metadata only (binary-search count — the
// proven variant; prep arithmetic is NOT the wall-clock bottleneck, shown by
// R10/R12/R14 invariance under 16/6/0-division implementations).
// Mask predicate is a prefix in w:  __fdiv_rn(w,sc) < lim  (IEEE division
// monotone in numerator; lim is an integer-valued float).
// ---------------------------------------------------------------------------
__global__ void __launch_bounds__(1024) k_prep(const float* __restrict__ scales,
                                               const int*   __restrict__ len_seq,
                                               const int*   __restrict__ len_seg_raw) {
    __shared__ int sseg[RR];
    __shared__ int soff[RR];
    __shared__ int s_wsum[32];
    __shared__ int s_wbase[32];
    const int tid  = threadIdx.x;
    const int lane = tid & 31;
    const int wid  = tid >> 5;

    for (int i = tid; i < RR; i += 1024) sseg[i] = len_seg_raw[i] + 32; // +MIN_LEN_SEG
    __syncthreads();

    if (wid < BB) {                      // warp-per-batch exclusive scan of 65 seg lens
        const int base = wid * SS;
        int carry = 0;
        #pragma unroll
        for (int c = 0; c < 3; c++) {
            const int s = c * 32 + lane;
            int v = (s < SS) ? sseg[base + s] : 0;
            int inc = v;
            #pragma unroll
            for (int d = 1; d < 32; d <<= 1) {
                const int n = __shfl_up_sync(0xffffffffu, inc, d);
                if (lane >= d) inc += n;
            }
            if (s < SS) soff[base + s] = carry + inc - v;
            carry += __shfl_sync(0xffffffffu, inc, 31);
        }
    }
    __syncthreads();

    // Two ordered rows per thread -> counts via 8-step binary search, local scan.
    int cnt[2], loc[2];
    int run = 0;
    #pragma unroll
    for (int j = 0; j < 2; j++) {
        const int r = tid * 2 + j;
        int c = 0;
        if (r < RR) {
            const float sc  = scales[r] + 0.5f;
            const int   off = soff[r];
            const int   ls  = len_seq[r / SS];
            const float lim = fminf((float)(sseg[r] - 1),
                                    (float)(ls - 1) - (float)off);
            int lo = 0, hi = WW;         // pred(w) = __fdiv_rn(w,sc) < lim, prefix-true
            #pragma unroll
            for (int it = 0; it < 8; it++) {
                const int mid = (lo + hi) >> 1;
                if (__fdiv_rn((float)mid, sc) < lim) lo = mid + 1; else hi = mid;
            }
            c = lo;
        }
        loc[j] = run; run += c; cnt[j] = c;
    }
    int inc = run;
    #pragma unroll
    for (int d = 1; d < 32; d <<= 1) {
        const int n = __shfl_up_sync(0xffffffffu, inc, d);
        if (lane >= d) inc += n;
    }
    const int texcl = inc - run;
    if (lane == 31) s_wsum[wid] = inc;
    __syncthreads();
    if (tid == 0) {
        int acc = 0;
        #pragma unroll
        for (int i = 0; i < 32; i++) { s_wbase[i] = acc; acc += s_wsum[i]; }
        g_meta[0] = acc;
        g_meta[1] = acc / BB;            // L = total // B
    }
    __syncthreads();
    const int base = s_wbase[wid] + texcl;
    #pragma unroll
    for (int j = 0; j < 2; j++) {
        const int r = tid * 2 + j;
        if (r < RR) {
            g_info[r] = make_int4(__float_as_int(scales[r] + 0.5f),
                                  (r / SS) * TT + soff[r],
                                  base + loc[j],
                                  cnt[j]);
        }
    }
}

// ---------------------------------------------------------------------------
// k_emit: 130 blocks x 8 warps = warp-per-row. Lanes sweep w in [0, count):
//   rec = { g = (ibase + floor(w/sc)) * 32,  lam = w/sc - floor }
// Masked entries satisfy idx_org < len_seq-1 < TT-1, so no clamps and
// i1 = i0 + 1 unconditionally. Divisions spread across 130 SMs.
// ---------------------------------------------------------------------------
__global__ void __launch_bounds__(256) k_emit() {
    const int r    = blockIdx.x * 8 + (threadIdx.x >> 5);   // 130*8 = RR exactly
    const int lane = threadIdx.x & 31;

    const int4  info  = g_info[r];
    const float sc    = __int_as_float(info.x);
    const int   ibase = info.y;
    const int   rs    = info.z;
    const int   cn    = info.w;

    for (int w = lane; w < cn; w += 32) {
        const float ws  = __fdiv_rn((float)w, sc);
        const float ifl = floorf(ws);
        g_rec[rs + w] = make_int2((ibase + (int)ifl) * (DD / 4),
                                  __float_as_int(ws - ifl));
    }
}

// ---------------------------------------------------------------------------
// k_main: ONE wave of 592 blocks.
//   Preamble: grid-stride predicated zero-fill of the t >= L tail (out is
//             poisoned to 0xAA). Disjoint from gather writes (t < L).
//   Body:     grid-stride over compacted slots; one warp = 4 consecutive
//             slots: 2 uniform 16B record loads, 8 gather LDG.128, 4 STG.128.
// ---------------------------------------------------------------------------
__global__ void __launch_bounds__(256)
k_main(const float* __restrict__ x,
       float* __restrict__ out) {
    const int L     = g_meta[1];
    const int total = g_meta[0];

    // ---- zero-fill preamble (covers everything when L <= 0) ----
    if (L < OUT_T) {
        const float4 z = make_float4(0.f, 0.f, 0.f, 0.f);
        for (unsigned i = blockIdx.x * 256u + threadIdx.x; i < NF4;
             i += (unsigned)NMAIN * 256u) {
            const int t = (int)((i >> 5) & (OUT_T - 1));   // 32 float4 per out row
            if (t >= L) ((float4*)out)[i] = z;
        }
    }
    if (L <= 0) return;

    const int lane = threadIdx.x & 31;
    const int gw   = blockIdx.x * 8 + (threadIdx.x >> 5);  // global warp id
    const float4* __restrict__ x4 = (const float4*)x;

    for (int p0 = gw * 4; p0 < total; p0 += NMAIN * 8 * 4) {
        // 4 consecutive records = 32B; p0 % 4 == 0 so both int4 reads are
        // 16B-aligned and stay inside g_rec (RR*WW is a multiple of 4).
        const int4 r01 = *(const int4*)(g_rec + p0);
        const int4 r23 = *(const int4*)(g_rec + p0 + 2);
        const int   gx[4] = { r01.x, r01.z, r23.x, r23.z };
        const float lm[4] = { __int_as_float(r01.y), __int_as_float(r01.w),
                              __int_as_float(r23.y), __int_as_float(r23.w) };

        const int bo0 = p0 / L;
        const int t0  = p0 - bo0 * L;
        const int oidx0 = (bo0 * OUT_T + t0) * (DD / 4) + lane;
        const int wrapk = L - t0;                     // k >= wrapk -> next batch

        float4 a[4], c[4];
        int    vv[4], oidx[4];
        #pragma unroll
        for (int k = 0; k < 4; k++) {
            const bool wrapped = (k >= wrapk);
            const int  bo = bo0 + (wrapped ? 1 : 0);
            const int  t  = t0 + k - (wrapped ? L : 0);   // k < 4 << L
            const bool ok = (p0 + k < total) && (bo < BB) && (t < OUT_T);
            vv[k]   = ok;
            oidx[k] = oidx0 + k * (DD / 4) + (wrapped ? (OUT_T - L) * (DD / 4) : 0);
            if (ok) {
                const int g = gx[k] + lane;
                a[k] = x4[g];
                c[k] = x4[g + (DD / 4)];
            }
        }
        #pragma unroll
        for (int k = 0; k < 4; k++) {
            if (vv[k]) {
                const float l = lm[k], m = 1.0f - l;
                float4 y;
                y.x = m * a[k].x + l * c[k].x;
                y.y = m * a[k].y + l * c[k].y;
                y.z = m * a[k].z + l * c[k].z;
                y.w = m * a[k].w + l * c[k].w;
                ((float4*)out)[oidx[k]] = y;
            }
        }
    }
}

// ---------------------------------------------------------------------------
extern "C" void kernel_launch(void* const* d_in, const int* in_sizes, int n_in,
                              void* d_out, int out_size) {
    const float* x           = (const float*)d_in[0];
    const float* scales      = (const float*)d_in[1];
    const int*   len_seq     = (const int*)d_in[2];
    const int*   len_seg_raw = (const int*)d_in[3];
    float*       out         = (float*)d_out;

    k_prep<<<1, 1024>>>(scales, len_seq, len_seg_raw);
    k_emit<<<RR / 8, 256>>>();
    k_main<<<NMAIN, 256>>>(x, out);
}